// round 10
// baseline (speedup 1.0000x reference)
#include <cuda_runtime.h>

#define NSTEPS 50
#define LRATE  0.1f
#define BMAX   8192

__device__ float g_c0[BMAX];

typedef unsigned long long u64;

__device__ __forceinline__ u64 pk2(float lo, float hi) {
    u64 r; asm("mov.b64 %0, {%1,%2};" : "=l"(r) : "f"(lo), "f"(hi)); return r;
}
__device__ __forceinline__ void upk2(u64 v, float& lo, float& hi) {
    asm("mov.b64 {%0,%1}, %2;" : "=f"(lo), "=f"(hi) : "l"(v));
}
__device__ __forceinline__ void fma2(u64& d, u64 a, u64 b) {
    asm("fma.rn.f32x2 %0, %1, %2, %0;" : "+l"(d) : "l"(a), "l"(b));
}

// ---------------------------------------------------------------------------
// Kernel 1: 1-D nearest neighbor (|ci-cj| == sqrt((ci-cj)^2) exactly in RN).
// ---------------------------------------------------------------------------
#define NN_TILE 2048
__global__ __launch_bounds__(256) void nn_kernel(const float* __restrict__ c, int B) {
    __shared__ float ct[NN_TILE];
    int lane = threadIdx.x & 31;
    int w    = threadIdx.x >> 5;
    int q    = blockIdx.x * 8 + w;
    float cq = (q < B) ? c[q] : 0.f;
    float bestD = 3.0e38f; int bestJ = 0;
    for (int t0 = 0; t0 < B; t0 += NN_TILE) {
        int nt = min(NN_TILE, B - t0);
        __syncthreads();
        for (int i = threadIdx.x; i < nt; i += 256) ct[i] = c[t0 + i];
        __syncthreads();
        for (int jj = lane; jj < nt; jj += 32) {
            int j = t0 + jj;
            float d = fabsf(cq - ct[jj]);
            if (j == q) d += 1e9f;
            if (d < bestD) { bestD = d; bestJ = j; }
        }
    }
#pragma unroll
    for (int off = 16; off; off >>= 1) {
        float dO = __shfl_down_sync(0xffffffffu, bestD, off);
        int   jO = __shfl_down_sync(0xffffffffu, bestJ, off);
        if (dO < bestD || (dO == bestD && jO < bestJ)) { bestD = dO; bestJ = jO; }
    }
    if (lane == 0 && q < B) g_c0[q] = c[bestJ];
}

// ---------------------------------------------------------------------------
// 64-k tile matvec: thread owns 4 neurons (2 f32x2 pairs) x 4 samples.
// acc[p*4+si]. Weights W[k][n] natural floats (row 64); acts A[k][32] dup u64,
// slot(si, sG) = (si>>1)*16 + sG*2 + (si&1).
// Per warp-k: 1 wf weights + 2 wf acts vs 8 FFMA2.
// ---------------------------------------------------------------------------
__device__ __forceinline__ void mv(const float* __restrict__ W,
                                   const u64* __restrict__ A,
                                   int n0, int sG2, u64 acc[8]) {
#pragma unroll 16
    for (int k = 0; k < 64; k++) {
        ulonglong2 wA  = *(const ulonglong2*)(W + k * 64 + n0);       // pairs 0,1
        ulonglong2 h01 = *(const ulonglong2*)(A + k * 32 + sG2);      // dup s0,s1
        ulonglong2 h23 = *(const ulonglong2*)(A + k * 32 + 16 + sG2); // dup s2,s3
        fma2(acc[0], wA.x, h01.x); fma2(acc[1], wA.x, h01.y);
        fma2(acc[2], wA.x, h23.x); fma2(acc[3], wA.x, h23.y);
        fma2(acc[4], wA.y, h01.x); fma2(acc[5], wA.y, h01.y);
        fma2(acc[6], wA.y, h23.x); fma2(acc[7], wA.y, h23.y);
    }
}

// acc -> v[r][si]  (r = neuron offset 0..3)
__device__ __forceinline__ void unpack(const u64 acc[8], float v[4][4]) {
#pragma unroll
    for (int p = 0; p < 2; p++)
#pragma unroll
        for (int si = 0; si < 4; si++)
            upk2(acc[p * 4 + si], v[2 * p][si], v[2 * p + 1][si]);
}

__device__ __forceinline__ void store_dup(u64* __restrict__ Y, int n0, int sG2,
                                          const float v[4][4]) {
#pragma unroll
    for (int r = 0; r < 4; r++) {
        ulonglong2 t0, t1;
        t0.x = pk2(v[r][0], v[r][0]); t0.y = pk2(v[r][1], v[r][1]);
        t1.x = pk2(v[r][2], v[r][2]); t1.y = pk2(v[r][3], v[r][3]);
        *(ulonglong2*)(Y + (n0 + r) * 32 + sG2)      = t0;
        *(ulonglong2*)(Y + (n0 + r) * 32 + 16 + sG2) = t1;
    }
}

// ---------------------------------------------------------------------------
// Kernel 2: block = 128 threads = 64 neurons x 32 samples; 2 blocks/SM.
// sG = tid&7 (8 sample-groups of 4), nQ = tid>>3 (16 neuron-groups of 4).
// ---------------------------------------------------------------------------
__global__ __launch_bounds__(128, 2) void solver_kernel(
    const float* __restrict__ x,
    const float* __restrict__ W1, const float* __restrict__ b1,
    const float* __restrict__ W2, const float* __restrict__ b2,
    const float* __restrict__ W3, const float* __restrict__ b3,
    const float* __restrict__ W4,
    float* __restrict__ out)
{
    extern __shared__ __align__(16) char smraw[];
    float* W2T = (float*)smraw;                 // [64][64] W2T[k][n]=W2[n][k]
    float* W3T = W2T + 4096;
    float* W2N = W3T + 4096;                    // natural
    float* W3N = W2N + 4096;
    u64*  ActA = (u64*)(W3N + 4096);            // [64][32] dup
    u64*  ActB = ActA + 2048;
    u64*  b2d  = ActB + 2048;                   // [32] f32x2 bias pairs
    u64*  b3d  = b2d + 32;
    float* red = (float*)(b3d + 32);            // [4][32]

    int tid = threadIdx.x;
    int lane = tid & 31, warp = tid >> 5;
    int sG = tid & 7, nQ = tid >> 3;
    int n0 = nQ * 4, sG2 = sG * 2;

    for (int i = tid; i < 1024; i += 128) {
        ((float4*)W2N)[i] = ((const float4*)W2)[i];
        ((float4*)W3N)[i] = ((const float4*)W3)[i];
    }
    __syncthreads();
    for (int i = tid; i < 4096; i += 128) {
        int n = i >> 6, k = i & 63;
        W2T[k * 64 + n] = W2N[i];
        W3T[k * 64 + n] = W3N[i];
    }
    if (tid < 32) {
        b2d[tid] = pk2(b2[2 * tid], b2[2 * tid + 1]);
        b3d[tid] = pk2(b3[2 * tid], b3[2 * tid + 1]);
    }

    int gs = blockIdx.x * 32 + sG * 4;          // this thread's 4 samples
    float xs[4], cs[4];
#pragma unroll
    for (int si = 0; si < 4; si++) { xs[si] = x[gs + si]; cs[si] = g_c0[gs + si]; }

    float a[4][4], w1y[4], w4r[4];
#pragma unroll
    for (int r = 0; r < 4; r++) {
        int n = n0 + r;
        float w1x = W1[n * 3 + 0]; w1y[r] = W1[n * 3 + 1];
        float w1c = W1[n * 3 + 2]; float bb = b1[n];
        w4r[r] = W4[n];
#pragma unroll
        for (int si = 0; si < 4; si++)
            a[r][si] = fmaf(w1x, xs[si], fmaf(w1c, cs[si], bb));
    }
    __syncthreads();

    float y[4] = {0.f, 0.f, 0.f, 0.f};          // Y_MEAN = 0

    for (int step = 0; step < NSTEPS; step++) {
        // ---- layer 1 (rank-1 in y) -> h1 ----
        unsigned m1 = 0;
        float v[4][4];
#pragma unroll
        for (int r = 0; r < 4; r++)
#pragma unroll
            for (int si = 0; si < 4; si++) {
                float z = fmaf(w1y[r], y[si], a[r][si]);
                if (z > 0.f) m1 |= 1u << (r * 4 + si);
                v[r][si] = fmaxf(z, 0.f);
            }
        store_dup(ActA, n0, sG2, v);
        __syncthreads();

        // ---- fwd2: z2 = W2 h1 + b2 ----
        u64 acc[8];
        {
            ulonglong2 bp = *(const ulonglong2*)(b2d + nQ * 2);
#pragma unroll
            for (int si = 0; si < 4; si++) { acc[si] = bp.x; acc[4 + si] = bp.y; }
        }
        mv(W2T, ActA, n0, sG2, acc);
        unsigned m2 = 0;
        unpack(acc, v);
#pragma unroll
        for (int r = 0; r < 4; r++)
#pragma unroll
            for (int si = 0; si < 4; si++) {
                if (v[r][si] > 0.f) m2 |= 1u << (r * 4 + si);
                v[r][si] = fmaxf(v[r][si], 0.f);
            }
        store_dup(ActB, n0, sG2, v);
        __syncthreads();

        // ---- fwd3: z3 = W3 h2 + b3 -> g3 = (z3>0)*W4 ----
        {
            ulonglong2 bp = *(const ulonglong2*)(b3d + nQ * 2);
#pragma unroll
            for (int si = 0; si < 4; si++) { acc[si] = bp.x; acc[4 + si] = bp.y; }
        }
        mv(W3T, ActB, n0, sG2, acc);
        unpack(acc, v);
#pragma unroll
        for (int r = 0; r < 4; r++)
#pragma unroll
            for (int si = 0; si < 4; si++)
                v[r][si] = (v[r][si] > 0.f) ? w4r[r] : 0.f;
        store_dup(ActA, n0, sG2, v);
        __syncthreads();

        // ---- bwd3: g2 = m2 .* (W3^T g3) ----
#pragma unroll
        for (int q = 0; q < 8; q++) acc[q] = 0;
        mv(W3N, ActA, n0, sG2, acc);
        unpack(acc, v);
#pragma unroll
        for (int r = 0; r < 4; r++)
#pragma unroll
            for (int si = 0; si < 4; si++)
                v[r][si] = (m2 & (1u << (r * 4 + si))) ? v[r][si] : 0.f;
        store_dup(ActB, n0, sG2, v);
        __syncthreads();

        // ---- bwd2: g1 = m1 .* (W2^T g2); gy = sum_n w1y[n] g1[n] ----
#pragma unroll
        for (int q = 0; q < 8; q++) acc[q] = 0;
        mv(W2N, ActB, n0, sG2, acc);
        unpack(acc, v);
        float pg[4] = {0.f, 0.f, 0.f, 0.f};
#pragma unroll
        for (int r = 0; r < 4; r++)
#pragma unroll
            for (int si = 0; si < 4; si++) {
                float g = (m1 & (1u << (r * 4 + si))) ? v[r][si] : 0.f;
                pg[si] = fmaf(w1y[r], g, pg[si]);
            }
        // combine the warp's 4 neuron-quads (lane bits 3,4)
#pragma unroll
        for (int si = 0; si < 4; si++) {
            pg[si] += __shfl_xor_sync(0xffffffffu, pg[si], 8);
            pg[si] += __shfl_xor_sync(0xffffffffu, pg[si], 16);
        }
        if (lane < 8) {
            float4 t = make_float4(pg[0], pg[1], pg[2], pg[3]);
            *(float4*)(red + warp * 32 + sG * 4) = t;
        }
        __syncthreads();
        {
            float4 r0 = *(const float4*)(red + 0 * 32 + sG * 4);
            float4 r1 = *(const float4*)(red + 1 * 32 + sG * 4);
            float4 r2 = *(const float4*)(red + 2 * 32 + sG * 4);
            float4 r3 = *(const float4*)(red + 3 * 32 + sG * 4);
            y[0] -= LRATE * ((r0.x + r1.x) + (r2.x + r3.x));
            y[1] -= LRATE * ((r0.y + r1.y) + (r2.y + r3.y));
            y[2] -= LRATE * ((r0.z + r1.z) + (r2.z + r3.z));
            y[3] -= LRATE * ((r0.w + r1.w) + (r2.w + r3.w));
        }
    }

    if (nQ == 0) {
        float4 t = make_float4(y[0], y[1], y[2], y[3]);
        *(float4*)(out + gs) = t;
    }
}

// ---------------------------------------------------------------------------
// Launch
// ---------------------------------------------------------------------------
extern "C" void kernel_launch(void* const* d_in, const int* in_sizes, int n_in,
                              void* d_out, int out_size) {
    const float* x  = (const float*)d_in[0];
    const float* c  = (const float*)d_in[1];
    const float* W1 = (const float*)d_in[2];
    const float* b1 = (const float*)d_in[3];
    const float* W2 = (const float*)d_in[4];
    const float* b2 = (const float*)d_in[5];
    const float* W3 = (const float*)d_in[6];
    const float* b3 = (const float*)d_in[7];
    const float* W4 = (const float*)d_in[8];
    // d_in[9] = b4: constant offset, no effect on dE/dy
    float* out = (float*)d_out;
    int B = in_sizes[0];

    // smem: 4*4096*4 (weights) + 2*2048*8 (acts) + 64*8 (bias) + 128*4 (red)
    const int SMEM = 4 * 4096 * 4 + 2 * 2048 * 8 + 64 * 8 + 128 * 4; // 99328 B
    cudaFuncSetAttribute(solver_kernel,
                         cudaFuncAttributeMaxDynamicSharedMemorySize, SMEM);

    nn_kernel<<<(B + 7) / 8, 256>>>(c, B);
    solver_kernel<<<B / 32, 128, SMEM>>>(x, W1, b1, W2, b2, W3, b3, W4, out);
}

// round 11
// speedup vs baseline: 1.0006x; 1.0006x over previous
#include <cuda_runtime.h>

#define NSTEPS 50
#define LRATE  0.1f
#define BMAX   8192

__device__ float g_c0[BMAX];

typedef unsigned long long u64;

__device__ __forceinline__ u64 pk2(float lo, float hi) {
    u64 r; asm("mov.b64 %0, {%1,%2};" : "=l"(r) : "f"(lo), "f"(hi)); return r;
}
__device__ __forceinline__ void upk2(u64 v, float& lo, float& hi) {
    asm("mov.b64 {%0,%1}, %2;" : "=f"(lo), "=f"(hi) : "l"(v));
}
__device__ __forceinline__ void fma2(u64& d, u64 a, u64 b) {
    asm("fma.rn.f32x2 %0, %1, %2, %0;" : "+l"(d) : "l"(a), "l"(b));
}

// ---------------------------------------------------------------------------
// Kernel 1: 1-D nearest neighbor (|ci-cj| == sqrt((ci-cj)^2) exactly in RN).
// ---------------------------------------------------------------------------
#define NN_TILE 2048
__global__ __launch_bounds__(256) void nn_kernel(const float* __restrict__ c, int B) {
    __shared__ float ct[NN_TILE];
    int lane = threadIdx.x & 31;
    int w    = threadIdx.x >> 5;
    int q    = blockIdx.x * 8 + w;
    float cq = (q < B) ? c[q] : 0.f;
    float bestD = 3.0e38f; int bestJ = 0;
    for (int t0 = 0; t0 < B; t0 += NN_TILE) {
        int nt = min(NN_TILE, B - t0);
        __syncthreads();
        for (int i = threadIdx.x; i < nt; i += 256) ct[i] = c[t0 + i];
        __syncthreads();
        for (int jj = lane; jj < nt; jj += 32) {
            int j = t0 + jj;
            float d = fabsf(cq - ct[jj]);
            if (j == q) d += 1e9f;
            if (d < bestD) { bestD = d; bestJ = j; }
        }
    }
#pragma unroll
    for (int off = 16; off; off >>= 1) {
        float dO = __shfl_down_sync(0xffffffffu, bestD, off);
        int   jO = __shfl_down_sync(0xffffffffu, bestJ, off);
        if (dO < bestD || (dO == bestD && jO < bestJ)) { bestD = dO; bestJ = jO; }
    }
    if (lane == 0 && q < B) g_c0[q] = c[bestJ];
}

// ---------------------------------------------------------------------------
// 64-k tile matvec: thread owns 4 neurons (2 f32x2 pairs) x 4 samples.
// acc[p*4+si]. Weights W[k][n] natural floats (row 64); acts A[k][32] dup u64,
// slot(si, sG) = (si>>1)*16 + sG*2 + (si&1).
// Per warp-k: 1 wf weights + 2 wf acts vs 8 FFMA2.
// ---------------------------------------------------------------------------
__device__ __forceinline__ void mv(const float* __restrict__ W,
                                   const u64* __restrict__ A,
                                   int n0, int sG2, u64 acc[8]) {
#pragma unroll 16
    for (int k = 0; k < 64; k++) {
        ulonglong2 wA  = *(const ulonglong2*)(W + k * 64 + n0);       // pairs 0,1
        ulonglong2 h01 = *(const ulonglong2*)(A + k * 32 + sG2);      // dup s0,s1
        ulonglong2 h23 = *(const ulonglong2*)(A + k * 32 + 16 + sG2); // dup s2,s3
        fma2(acc[0], wA.x, h01.x); fma2(acc[1], wA.x, h01.y);
        fma2(acc[2], wA.x, h23.x); fma2(acc[3], wA.x, h23.y);
        fma2(acc[4], wA.y, h01.x); fma2(acc[5], wA.y, h01.y);
        fma2(acc[6], wA.y, h23.x); fma2(acc[7], wA.y, h23.y);
    }
}

// acc -> v[r][si]  (r = neuron offset 0..3)
__device__ __forceinline__ void unpack(const u64 acc[8], float v[4][4]) {
#pragma unroll
    for (int p = 0; p < 2; p++)
#pragma unroll
        for (int si = 0; si < 4; si++)
            upk2(acc[p * 4 + si], v[2 * p][si], v[2 * p + 1][si]);
}

__device__ __forceinline__ void store_dup(u64* __restrict__ Y, int n0, int sG2,
                                          const float v[4][4]) {
#pragma unroll
    for (int r = 0; r < 4; r++) {
        ulonglong2 t0, t1;
        t0.x = pk2(v[r][0], v[r][0]); t0.y = pk2(v[r][1], v[r][1]);
        t1.x = pk2(v[r][2], v[r][2]); t1.y = pk2(v[r][3], v[r][3]);
        *(ulonglong2*)(Y + (n0 + r) * 32 + sG2)      = t0;
        *(ulonglong2*)(Y + (n0 + r) * 32 + 16 + sG2) = t1;
    }
}

// ---------------------------------------------------------------------------
// Kernel 2: block = 128 threads = 64 neurons x 32 samples; 2 blocks/SM.
// sG = tid&7 (8 sample-groups of 4), nQ = tid>>3 (16 neuron-groups of 4).
// ---------------------------------------------------------------------------
__global__ __launch_bounds__(128, 2) void solver_kernel(
    const float* __restrict__ x,
    const float* __restrict__ W1, const float* __restrict__ b1,
    const float* __restrict__ W2, const float* __restrict__ b2,
    const float* __restrict__ W3, const float* __restrict__ b3,
    const float* __restrict__ W4,
    float* __restrict__ out)
{
    extern __shared__ __align__(16) char smraw[];
    float* W2T = (float*)smraw;                 // [64][64] W2T[k][n]=W2[n][k]
    float* W3T = W2T + 4096;
    float* W2N = W3T + 4096;                    // natural
    float* W3N = W2N + 4096;
    u64*  ActA = (u64*)(W3N + 4096);            // [64][32] dup
    u64*  ActB = ActA + 2048;
    u64*  b2d  = ActB + 2048;                   // [32] f32x2 bias pairs
    u64*  b3d  = b2d + 32;
    float* red = (float*)(b3d + 32);            // [4][32]

    int tid = threadIdx.x;
    int lane = tid & 31, warp = tid >> 5;
    int sG = tid & 7, nQ = tid >> 3;
    int n0 = nQ * 4, sG2 = sG * 2;

    for (int i = tid; i < 1024; i += 128) {
        ((float4*)W2N)[i] = ((const float4*)W2)[i];
        ((float4*)W3N)[i] = ((const float4*)W3)[i];
    }
    __syncthreads();
    for (int i = tid; i < 4096; i += 128) {
        int n = i >> 6, k = i & 63;
        W2T[k * 64 + n] = W2N[i];
        W3T[k * 64 + n] = W3N[i];
    }
    if (tid < 32) {
        b2d[tid] = pk2(b2[2 * tid], b2[2 * tid + 1]);
        b3d[tid] = pk2(b3[2 * tid], b3[2 * tid + 1]);
    }

    int gs = blockIdx.x * 32 + sG * 4;          // this thread's 4 samples
    float xs[4], cs[4];
#pragma unroll
    for (int si = 0; si < 4; si++) { xs[si] = x[gs + si]; cs[si] = g_c0[gs + si]; }

    float a[4][4], w1y[4], w4r[4];
#pragma unroll
    for (int r = 0; r < 4; r++) {
        int n = n0 + r;
        float w1x = W1[n * 3 + 0]; w1y[r] = W1[n * 3 + 1];
        float w1c = W1[n * 3 + 2]; float bb = b1[n];
        w4r[r] = W4[n];
#pragma unroll
        for (int si = 0; si < 4; si++)
            a[r][si] = fmaf(w1x, xs[si], fmaf(w1c, cs[si], bb));
    }
    __syncthreads();

    float y[4] = {0.f, 0.f, 0.f, 0.f};          // Y_MEAN = 0

    for (int step = 0; step < NSTEPS; step++) {
        // ---- layer 1 (rank-1 in y) -> h1 ----
        unsigned m1 = 0;
        float v[4][4];
#pragma unroll
        for (int r = 0; r < 4; r++)
#pragma unroll
            for (int si = 0; si < 4; si++) {
                float z = fmaf(w1y[r], y[si], a[r][si]);
                if (z > 0.f) m1 |= 1u << (r * 4 + si);
                v[r][si] = fmaxf(z, 0.f);
            }
        store_dup(ActA, n0, sG2, v);
        __syncthreads();

        // ---- fwd2: z2 = W2 h1 + b2 ----
        u64 acc[8];
        {
            ulonglong2 bp = *(const ulonglong2*)(b2d + nQ * 2);
#pragma unroll
            for (int si = 0; si < 4; si++) { acc[si] = bp.x; acc[4 + si] = bp.y; }
        }
        mv(W2T, ActA, n0, sG2, acc);
        unsigned m2 = 0;
        unpack(acc, v);
#pragma unroll
        for (int r = 0; r < 4; r++)
#pragma unroll
            for (int si = 0; si < 4; si++) {
                if (v[r][si] > 0.f) m2 |= 1u << (r * 4 + si);
                v[r][si] = fmaxf(v[r][si], 0.f);
            }
        store_dup(ActB, n0, sG2, v);
        __syncthreads();

        // ---- fwd3: z3 = W3 h2 + b3 -> g3 = (z3>0)*W4 ----
        {
            ulonglong2 bp = *(const ulonglong2*)(b3d + nQ * 2);
#pragma unroll
            for (int si = 0; si < 4; si++) { acc[si] = bp.x; acc[4 + si] = bp.y; }
        }
        mv(W3T, ActB, n0, sG2, acc);
        unpack(acc, v);
#pragma unroll
        for (int r = 0; r < 4; r++)
#pragma unroll
            for (int si = 0; si < 4; si++)
                v[r][si] = (v[r][si] > 0.f) ? w4r[r] : 0.f;
        store_dup(ActA, n0, sG2, v);
        __syncthreads();

        // ---- bwd3: g2 = m2 .* (W3^T g3) ----
#pragma unroll
        for (int q = 0; q < 8; q++) acc[q] = 0;
        mv(W3N, ActA, n0, sG2, acc);
        unpack(acc, v);
#pragma unroll
        for (int r = 0; r < 4; r++)
#pragma unroll
            for (int si = 0; si < 4; si++)
                v[r][si] = (m2 & (1u << (r * 4 + si))) ? v[r][si] : 0.f;
        store_dup(ActB, n0, sG2, v);
        __syncthreads();

        // ---- bwd2: g1 = m1 .* (W2^T g2); gy = sum_n w1y[n] g1[n] ----
#pragma unroll
        for (int q = 0; q < 8; q++) acc[q] = 0;
        mv(W2N, ActB, n0, sG2, acc);
        unpack(acc, v);
        float pg[4] = {0.f, 0.f, 0.f, 0.f};
#pragma unroll
        for (int r = 0; r < 4; r++)
#pragma unroll
            for (int si = 0; si < 4; si++) {
                float g = (m1 & (1u << (r * 4 + si))) ? v[r][si] : 0.f;
                pg[si] = fmaf(w1y[r], g, pg[si]);
            }
        // combine the warp's 4 neuron-quads (lane bits 3,4)
#pragma unroll
        for (int si = 0; si < 4; si++) {
            pg[si] += __shfl_xor_sync(0xffffffffu, pg[si], 8);
            pg[si] += __shfl_xor_sync(0xffffffffu, pg[si], 16);
        }
        if (lane < 8) {
            float4 t = make_float4(pg[0], pg[1], pg[2], pg[3]);
            *(float4*)(red + warp * 32 + sG * 4) = t;
        }
        __syncthreads();
        {
            float4 r0 = *(const float4*)(red + 0 * 32 + sG * 4);
            float4 r1 = *(const float4*)(red + 1 * 32 + sG * 4);
            float4 r2 = *(const float4*)(red + 2 * 32 + sG * 4);
            float4 r3 = *(const float4*)(red + 3 * 32 + sG * 4);
            y[0] -= LRATE * ((r0.x + r1.x) + (r2.x + r3.x));
            y[1] -= LRATE * ((r0.y + r1.y) + (r2.y + r3.y));
            y[2] -= LRATE * ((r0.z + r1.z) + (r2.z + r3.z));
            y[3] -= LRATE * ((r0.w + r1.w) + (r2.w + r3.w));
        }
    }

    if (nQ == 0) {
        float4 t = make_float4(y[0], y[1], y[2], y[3]);
        *(float4*)(out + gs) = t;
    }
}

// ---------------------------------------------------------------------------
// Launch
// ---------------------------------------------------------------------------
extern "C" void kernel_launch(void* const* d_in, const int* in_sizes, int n_in,
                              void* d_out, int out_size) {
    const float* x  = (const float*)d_in[0];
    const float* c  = (const float*)d_in[1];
    const float* W1 = (const float*)d_in[2];
    const float* b1 = (const float*)d_in[3];
    const float* W2 = (const float*)d_in[4];
    const float* b2 = (const float*)d_in[5];
    const float* W3 = (const float*)d_in[6];
    const float* b3 = (const float*)d_in[7];
    const float* W4 = (const float*)d_in[8];
    // d_in[9] = b4: constant offset, no effect on dE/dy
    float* out = (float*)d_out;
    int B = in_sizes[0];

    // smem: 4*4096*4 (weights) + 2*2048*8 (acts) + 64*8 (bias) + 128*4 (red)
    const int SMEM = 4 * 4096 * 4 + 2 * 2048 * 8 + 64 * 8 + 128 * 4; // 99328 B
    cudaFuncSetAttribute(solver_kernel,
                         cudaFuncAttributeMaxDynamicSharedMemorySize, SMEM);

    nn_kernel<<<(B + 7) / 8, 256>>>(c, B);
    solver_kernel<<<B / 32, 128, SMEM>>>(x, W1, b1, W2, b2, W3, b3, W4, out);
}

// round 14
// speedup vs baseline: 1.5719x; 1.5710x over previous
#include <cuda_runtime.h>

#define NSTEPS   50
#define T_DENSE  16
#define T_CACHED (NSTEPS - T_DENSE)
#define LRATE    0.1f
#define BMAX     8192

__device__ float g_c0[BMAX];
typedef unsigned long long u64;

__device__ __forceinline__ u64 pk2(float lo, float hi) {
    u64 r; asm("mov.b64 %0, {%1,%2};" : "=l"(r) : "f"(lo), "f"(hi)); return r;
}
__device__ __forceinline__ void upk2(u64 v, float& lo, float& hi) {
    asm("mov.b64 {%0,%1}, %2;" : "=f"(lo), "=f"(hi) : "l"(v));
}
__device__ __forceinline__ void fma2(u64& d, u64 a, u64 b) {
    asm("fma.rn.f32x2 %0, %1, %2, %0;" : "+l"(d) : "l"(a), "l"(b));
}

// ---------------- Kernel 1: 1-D nearest neighbor ----------------
#define NN_TILE 2048
__global__ __launch_bounds__(256) void nn_kernel(const float* __restrict__ c, int B) {
    __shared__ float ct[NN_TILE];
    int lane = threadIdx.x & 31, w = threadIdx.x >> 5, q = blockIdx.x * 8 + w;
    float cq = (q < B) ? c[q] : 0.f;
    float bestD = 3.0e38f; int bestJ = 0;
    for (int t0 = 0; t0 < B; t0 += NN_TILE) {
        int nt = min(NN_TILE, B - t0);
        __syncthreads();
        for (int i = threadIdx.x; i < nt; i += 256) ct[i] = c[t0 + i];
        __syncthreads();
        for (int jj = lane; jj < nt; jj += 32) {
            int j = t0 + jj;
            float d = fabsf(cq - ct[jj]);
            if (j == q) d += 1e9f;
            if (d < bestD) { bestD = d; bestJ = j; }
        }
    }
#pragma unroll
    for (int off = 16; off; off >>= 1) {
        float dO = __shfl_down_sync(0xffffffffu, bestD, off);
        int   jO = __shfl_down_sync(0xffffffffu, bestJ, off);
        if (dO < bestD || (dO == bestD && jO < bestJ)) { bestD = dO; bestJ = jO; }
    }
    if (lane == 0 && q < B) g_c0[q] = c[bestJ];
}

// ---------------- Phase 1: dense (R4 winner), nsteps param ----------------
__device__ __forceinline__ void mv_d(const float* __restrict__ W,
                                     const u64* __restrict__ A,
                                     int n0, int sG2, u64 acc[16]) {
#pragma unroll 8
    for (int k = 0; k < 64; k++) {
        ulonglong2 wA  = *(const ulonglong2*)(W + k * 64 + n0);
        ulonglong2 wB  = *(const ulonglong2*)(W + k * 64 + n0 + 4);
        ulonglong2 h01 = *(const ulonglong2*)(A + k * 64 + sG2);
        ulonglong2 h23 = *(const ulonglong2*)(A + k * 64 + 32 + sG2);
        fma2(acc[0],  wA.x, h01.x); fma2(acc[1],  wA.x, h01.y);
        fma2(acc[2],  wA.x, h23.x); fma2(acc[3],  wA.x, h23.y);
        fma2(acc[4],  wA.y, h01.x); fma2(acc[5],  wA.y, h01.y);
        fma2(acc[6],  wA.y, h23.x); fma2(acc[7],  wA.y, h23.y);
        fma2(acc[8],  wB.x, h01.x); fma2(acc[9],  wB.x, h01.y);
        fma2(acc[10], wB.x, h23.x); fma2(acc[11], wB.x, h23.y);
        fma2(acc[12], wB.y, h01.x); fma2(acc[13], wB.y, h01.y);
        fma2(acc[14], wB.y, h23.x); fma2(acc[15], wB.y, h23.y);
    }
}
__device__ __forceinline__ void unpack_d(const u64 acc[16], float v[8][4]) {
#pragma unroll
    for (int p = 0; p < 4; p++)
#pragma unroll
        for (int si = 0; si < 4; si++)
            upk2(acc[p * 4 + si], v[2 * p][si], v[2 * p + 1][si]);
}
__device__ __forceinline__ void store_dup_d(u64* __restrict__ Y, int n0, int sG2,
                                            const float v[8][4]) {
#pragma unroll
    for (int r = 0; r < 8; r++) {
        ulonglong2 t0, t1;
        t0.x = pk2(v[r][0], v[r][0]); t0.y = pk2(v[r][1], v[r][1]);
        t1.x = pk2(v[r][2], v[r][2]); t1.y = pk2(v[r][3], v[r][3]);
        *(ulonglong2*)(Y + (n0 + r) * 64 + sG2)      = t0;
        *(ulonglong2*)(Y + (n0 + r) * 64 + 32 + sG2) = t1;
    }
}

__global__ __launch_bounds__(128, 1) void solver_dense(
    const float* __restrict__ x,
    const float* __restrict__ W1, const float* __restrict__ b1,
    const float* __restrict__ W2, const float* __restrict__ b2,
    const float* __restrict__ W3, const float* __restrict__ b3,
    const float* __restrict__ W4, float* __restrict__ out, int nsteps)
{
    extern __shared__ __align__(16) char smraw[];
    float* W2T = (float*)smraw;
    float* W3T = W2T + 4096;
    float* W2N = W3T + 4096;
    float* W3N = W2N + 4096;
    u64*  ActA = (u64*)(W3N + 4096);
    u64*  ActB = ActA + 4096;
    u64*  b2d  = ActB + 4096;
    u64*  b3d  = b2d + 32;
    float* red = (float*)(b3d + 32);

    int tid = threadIdx.x, lane = tid & 31, warp = tid >> 5;
    int sG = tid & 15, nG = tid >> 4, n0 = nG * 8, sG2 = sG * 2;

    for (int i = tid; i < 1024; i += 128) {
        ((float4*)W2N)[i] = ((const float4*)W2)[i];
        ((float4*)W3N)[i] = ((const float4*)W3)[i];
    }
    __syncthreads();
    for (int i = tid; i < 4096; i += 128) {
        int n = i >> 6, k = i & 63;
        W2T[k * 64 + n] = W2N[i];
        W3T[k * 64 + n] = W3N[i];
    }
    if (tid < 32) {
        b2d[tid] = pk2(b2[2 * tid], b2[2 * tid + 1]);
        b3d[tid] = pk2(b3[2 * tid], b3[2 * tid + 1]);
    }

    int gs = blockIdx.x * 64 + sG * 4;
    float xs[4], cs[4];
#pragma unroll
    for (int si = 0; si < 4; si++) { xs[si] = x[gs + si]; cs[si] = g_c0[gs + si]; }
    float a[8][4], w1y[8], w4r[8];
#pragma unroll
    for (int r = 0; r < 8; r++) {
        int n = n0 + r;
        float w1x = W1[n * 3], w1c = W1[n * 3 + 2], bb = b1[n];
        w1y[r] = W1[n * 3 + 1]; w4r[r] = W4[n];
#pragma unroll
        for (int si = 0; si < 4; si++)
            a[r][si] = fmaf(w1x, xs[si], fmaf(w1c, cs[si], bb));
    }
    __syncthreads();

    float y[4] = {0.f, 0.f, 0.f, 0.f};
    for (int step = 0; step < nsteps; step++) {
        unsigned m1 = 0;
        float v[8][4];
#pragma unroll
        for (int r = 0; r < 8; r++)
#pragma unroll
            for (int si = 0; si < 4; si++) {
                float z = fmaf(w1y[r], y[si], a[r][si]);
                if (z > 0.f) m1 |= 1u << (r * 4 + si);
                v[r][si] = fmaxf(z, 0.f);
            }
        store_dup_d(ActA, n0, sG2, v);
        __syncthreads();

        u64 acc[16];
        {
            ulonglong2 ba = *(const ulonglong2*)(b2d + nG * 4);
            ulonglong2 bb = *(const ulonglong2*)(b2d + nG * 4 + 2);
#pragma unroll
            for (int si = 0; si < 4; si++) {
                acc[si] = ba.x; acc[4 + si] = ba.y;
                acc[8 + si] = bb.x; acc[12 + si] = bb.y;
            }
        }
        mv_d(W2T, ActA, n0, sG2, acc);
        unsigned m2 = 0;
        unpack_d(acc, v);
#pragma unroll
        for (int r = 0; r < 8; r++)
#pragma unroll
            for (int si = 0; si < 4; si++) {
                if (v[r][si] > 0.f) m2 |= 1u << (r * 4 + si);
                v[r][si] = fmaxf(v[r][si], 0.f);
            }
        store_dup_d(ActB, n0, sG2, v);
        __syncthreads();

        {
            ulonglong2 ba = *(const ulonglong2*)(b3d + nG * 4);
            ulonglong2 bb = *(const ulonglong2*)(b3d + nG * 4 + 2);
#pragma unroll
            for (int si = 0; si < 4; si++) {
                acc[si] = ba.x; acc[4 + si] = ba.y;
                acc[8 + si] = bb.x; acc[12 + si] = bb.y;
            }
        }
        mv_d(W3T, ActB, n0, sG2, acc);
        unpack_d(acc, v);
#pragma unroll
        for (int r = 0; r < 8; r++)
#pragma unroll
            for (int si = 0; si < 4; si++)
                v[r][si] = (v[r][si] > 0.f) ? w4r[r] : 0.f;
        store_dup_d(ActA, n0, sG2, v);
        __syncthreads();

#pragma unroll
        for (int q = 0; q < 16; q++) acc[q] = 0;
        mv_d(W3N, ActA, n0, sG2, acc);
        unpack_d(acc, v);
#pragma unroll
        for (int r = 0; r < 8; r++)
#pragma unroll
            for (int si = 0; si < 4; si++)
                v[r][si] = (m2 & (1u << (r * 4 + si))) ? v[r][si] : 0.f;
        store_dup_d(ActB, n0, sG2, v);
        __syncthreads();

#pragma unroll
        for (int q = 0; q < 16; q++) acc[q] = 0;
        mv_d(W2N, ActB, n0, sG2, acc);
        unpack_d(acc, v);
        float pg[4] = {0.f, 0.f, 0.f, 0.f};
#pragma unroll
        for (int r = 0; r < 8; r++)
#pragma unroll
            for (int si = 0; si < 4; si++) {
                float g = (m1 & (1u << (r * 4 + si))) ? v[r][si] : 0.f;
                pg[si] = fmaf(w1y[r], g, pg[si]);
            }
#pragma unroll
        for (int si = 0; si < 4; si++)
            pg[si] += __shfl_xor_sync(0xffffffffu, pg[si], 16);
        if (!(lane & 16))
            *(float4*)(red + warp * 64 + sG * 4) = make_float4(pg[0], pg[1], pg[2], pg[3]);
        __syncthreads();
        {
            float4 r0 = *(const float4*)(red + 0 * 64 + sG * 4);
            float4 r1 = *(const float4*)(red + 1 * 64 + sG * 4);
            float4 r2 = *(const float4*)(red + 2 * 64 + sG * 4);
            float4 r3 = *(const float4*)(red + 3 * 64 + sG * 4);
            y[0] -= LRATE * ((r0.x + r1.x) + (r2.x + r3.x));
            y[1] -= LRATE * ((r0.y + r1.y) + (r2.y + r3.y));
            y[2] -= LRATE * ((r0.z + r1.z) + (r2.z + r3.z));
            y[3] -= LRATE * ((r0.w + r1.w) + (r2.w + r3.w));
        }
    }
    if (nG == 0)
        *(float4*)(out + gs) = make_float4(y[0], y[1], y[2], y[3]);
}

// ---------------- Phase 2: mask-region cached stepping ----------------
// Warp owns 8 samples; lane np owns neuron pair (2np, 2np+1).
__global__ __launch_bounds__(256, 1) void solver_cached(
    const float* __restrict__ x,
    const float* __restrict__ W1, const float* __restrict__ b1,
    const float* __restrict__ W2, const float* __restrict__ b2,
    const float* __restrict__ W3, const float* __restrict__ b3,
    const float* __restrict__ W4, float* __restrict__ out)
{
    extern __shared__ __align__(16) char sm[];
    float* W2T = (float*)sm;
    float* W3T = W2T + 4096;
    float* W2N = W3T + 4096;
    float* W3N = W2N + 4096;
    u64*   b2p = (u64*)(W3N + 4096);
    u64*   b3p = b2p + 32;
    ulonglong2* RP2 = (ulonglong2*)(b3p + 32);   // [128 entries][32 lanes]
    ulonglong2* RP3 = RP2 + 128 * 32;
    float2* SCF = (float2*)(RP3 + 128 * 32);     // [8 warps][64]
    u64*   MK  = (u64*)(SCF + 8 * 64);           // [128][3]
    float* GY  = (float*)(MK + 128 * 3);         // [128]
    unsigned* VAL = (unsigned*)(GY + 128);       // [128]
    unsigned* MRU = VAL + 128;                   // [64]

    int tid = threadIdx.x, np = tid & 31, w = tid >> 5;

    for (int i = tid; i < 1024; i += 256) {
        ((float4*)W2N)[i] = ((const float4*)W2)[i];
        ((float4*)W3N)[i] = ((const float4*)W3)[i];
    }
    __syncthreads();
    for (int i = tid; i < 4096; i += 256) {
        int n = i >> 6, k = i & 63;
        W2T[k * 64 + n] = W2N[i];
        W3T[k * 64 + n] = W3N[i];
    }
    if (tid < 32) {
        b2p[tid] = pk2(b2[2 * tid], b2[2 * tid + 1]);
        b3p[tid] = pk2(b3[2 * tid], b3[2 * tid + 1]);
    }
    if (tid < 128) VAL[tid] = 0;
    if (tid < 64)  MRU[tid] = 0;
    __syncthreads();

    int gs = blockIdx.x * 64 + w * 8;
    float wy_lo = W1[(2 * np) * 3 + 1], wy_hi = W1[(2 * np + 1) * 3 + 1];
    u64 w1yp = pk2(wy_lo, wy_hi);
    float w4lo = W4[2 * np], w4hi = W4[2 * np + 1];
    float a_lo0 = W1[(2 * np) * 3], a_c0 = W1[(2 * np) * 3 + 2], bb0 = b1[2 * np];
    float a_lo1 = W1[(2 * np + 1) * 3], a_c1 = W1[(2 * np + 1) * 3 + 2], bb1 = b1[2 * np + 1];

    u64 ap[8]; float ys[8];
#pragma unroll
    for (int s = 0; s < 8; s++) {
        float xv = x[gs + s], cv = g_c0[gs + s];
        ap[s] = pk2(fmaf(a_lo0, xv, fmaf(a_c0, cv, bb0)),
                    fmaf(a_lo1, xv, fmaf(a_c1, cv, bb1)));
        ys[s] = out[gs + s];
    }
    float2* scf = SCF + w * 64;
    float*  scu = (float*)scf;

    for (int t = 0; t < T_CACHED; t++) {
#pragma unroll 1
        for (int s = 0; s < 8; s++) {
            float y = ys[s];
            u64 ydup = pk2(y, y);
            u64 z1 = ap[s]; fma2(z1, w1yp, ydup);
            float z1lo, z1hi; upk2(z1, z1lo, z1hi);
            unsigned q1l = __ballot_sync(0xffffffffu, z1lo > 0.f);
            unsigned q1h = __ballot_sync(0xffffffffu, z1hi > 0.f);
            u64 M1 = (u64)q1l | ((u64)q1h << 32);

            int e0 = (int)MRU[w * 8 + s];
            int hit = -1;
#pragma unroll
            for (int tr = 0; tr < 2; tr++) {
                int e = e0 ^ tr, base = (w * 2 + e) * 8 + s;
                if (!VAL[base] || MK[base * 3] != M1) continue;
                ulonglong2 rp2 = RP2[base * 32 + np];
                u64 z2 = rp2.x; fma2(z2, rp2.y, ydup);
                float lo, hi; upk2(z2, lo, hi);
                unsigned a2l = __ballot_sync(0xffffffffu, lo > 0.f);
                unsigned a2h = __ballot_sync(0xffffffffu, hi > 0.f);
                if ((((u64)a2l | ((u64)a2h << 32))) != MK[base * 3 + 1]) continue;
                ulonglong2 rp3 = RP3[base * 32 + np];
                u64 z3 = rp3.x; fma2(z3, rp3.y, ydup);
                upk2(z3, lo, hi);
                unsigned a3l = __ballot_sync(0xffffffffu, lo > 0.f);
                unsigned a3h = __ballot_sync(0xffffffffu, hi > 0.f);
                if ((((u64)a3l | ((u64)a3h << 32))) != MK[base * 3 + 2]) continue;
                hit = e; break;
            }

            if (hit >= 0) {
                ys[s] = y - LRATE * GY[(w * 2 + hit) * 8 + s];
                MRU[w * 8 + s] = (unsigned)hit;
            } else {
                // ---- cold rebuild into LRU entry ----
                int e = e0 ^ 1, base = (w * 2 + e) * 8 + s;
                float alo, ahi; upk2(ap[s], alo, ahi);
                bool m1lo = (q1l >> np) & 1, m1hi = (q1h >> np) & 1;
                scf[2 * np]     = make_float2(m1lo ? alo : 0.f, m1lo ? wy_lo : 0.f);
                scf[2 * np + 1] = make_float2(m1hi ? ahi : 0.f, m1hi ? wy_hi : 0.f);
                __syncwarp();
                u64 aR = b2p[np], aP = 0;
#pragma unroll 4
                for (int k = 0; k < 64; k++) {
                    float2 tt = scf[k];
                    u64 wp = *(const u64*)(W2T + k * 64 + 2 * np);
                    fma2(aR, wp, pk2(tt.x, tt.x));
                    fma2(aP, wp, pk2(tt.y, tt.y));
                }
                { ulonglong2 rp; rp.x = aR; rp.y = aP; RP2[base * 32 + np] = rp; }
                u64 z2 = aR; fma2(z2, aP, ydup);
                float z2lo, z2hi; upk2(z2, z2lo, z2hi);
                unsigned q2l = __ballot_sync(0xffffffffu, z2lo > 0.f);
                unsigned q2h = __ballot_sync(0xffffffffu, z2hi > 0.f);
                bool m2lo = (q2l >> np) & 1, m2hi = (q2h >> np) & 1;
                float rlo, rhi, plo, phi; upk2(aR, rlo, rhi); upk2(aP, plo, phi);
                __syncwarp();
                scf[2 * np]     = make_float2(m2lo ? rlo : 0.f, m2lo ? plo : 0.f);
                scf[2 * np + 1] = make_float2(m2hi ? rhi : 0.f, m2hi ? phi : 0.f);
                __syncwarp();
                u64 aR3 = b3p[np], aP3 = 0;
#pragma unroll 4
                for (int k = 0; k < 64; k++) {
                    float2 tt = scf[k];
                    u64 wp = *(const u64*)(W3T + k * 64 + 2 * np);
                    fma2(aR3, wp, pk2(tt.x, tt.x));
                    fma2(aP3, wp, pk2(tt.y, tt.y));
                }
                { ulonglong2 rp; rp.x = aR3; rp.y = aP3; RP3[base * 32 + np] = rp; }
                u64 z3 = aR3; fma2(z3, aP3, ydup);
                float z3lo, z3hi; upk2(z3, z3lo, z3hi);
                unsigned q3l = __ballot_sync(0xffffffffu, z3lo > 0.f);
                unsigned q3h = __ballot_sync(0xffffffffu, z3hi > 0.f);
                // backward (mask-only)
                __syncwarp();
                scu[2 * np]     = ((q3l >> np) & 1) ? w4lo : 0.f;
                scu[2 * np + 1] = ((q3h >> np) & 1) ? w4hi : 0.f;
                __syncwarp();
                u64 acc = 0;
#pragma unroll 4
                for (int j = 0; j < 64; j++) {
                    float uj = scu[j];
                    fma2(acc, *(const u64*)(W3N + j * 64 + 2 * np), pk2(uj, uj));
                }
                float tlo, thi; upk2(acc, tlo, thi);
                __syncwarp();
                scu[2 * np]     = m2lo ? tlo : 0.f;
                scu[2 * np + 1] = m2hi ? thi : 0.f;
                __syncwarp();
                acc = 0;
#pragma unroll 4
                for (int j = 0; j < 64; j++) {
                    float vj = scu[j];
                    fma2(acc, *(const u64*)(W2N + j * 64 + 2 * np), pk2(vj, vj));
                }
                float wlo, whi; upk2(acc, wlo, whi);
                float pg = (m1lo ? wy_lo * wlo : 0.f) + (m1hi ? wy_hi * whi : 0.f);
#pragma unroll
                for (int o = 1; o < 32; o <<= 1)
                    pg += __shfl_xor_sync(0xffffffffu, pg, o);
                if (np == 0) {
                    MK[base * 3]     = M1;
                    MK[base * 3 + 1] = (u64)q2l | ((u64)q2h << 32);
                    MK[base * 3 + 2] = (u64)q3l | ((u64)q3h << 32);
                    GY[base]  = pg;
                    VAL[base] = 1u;
                    MRU[w * 8 + s] = (unsigned)e;
                }
                __syncwarp();
                ys[s] = y - LRATE * pg;
            }
        }
    }

    if (np == 0) {
#pragma unroll
        for (int s = 0; s < 8; s++) out[gs + s] = ys[s];
    }
}

// ---------------- Launch ----------------
extern "C" void kernel_launch(void* const* d_in, const int* in_sizes, int n_in,
                              void* d_out, int out_size) {
    const float* x  = (const float*)d_in[0];
    const float* c  = (const float*)d_in[1];
    const float* W1 = (const float*)d_in[2];
    const float* b1 = (const float*)d_in[3];
    const float* W2 = (const float*)d_in[4];
    const float* b2 = (const float*)d_in[5];
    const float* W3 = (const float*)d_in[6];
    const float* b3 = (const float*)d_in[7];
    const float* W4 = (const float*)d_in[8];
    float* out = (float*)d_out;
    int B = in_sizes[0];

    const int SMEM_D = 4 * 4096 * 4 + 2 * 4096 * 8 + 64 * 8 + 256 * 4;   // 132608
    const int SMEM_C = 4 * 4096 * 4 + 64 * 8 + 2 * 128 * 32 * 16
                     + 8 * 64 * 8 + 128 * 24 + 128 * 4 + 128 * 4 + 64 * 4; // 205568
    cudaFuncSetAttribute(solver_dense,
                         cudaFuncAttributeMaxDynamicSharedMemorySize, SMEM_D);
    cudaFuncSetAttribute(solver_cached,
                         cudaFuncAttributeMaxDynamicSharedMemorySize, SMEM_C);

    nn_kernel<<<(B + 7) / 8, 256>>>(c, B);
    solver_dense<<<B / 64, 128, SMEM_D>>>(x, W1, b1, W2, b2, W3, b3, W4, out, T_DENSE);
    solver_cached<<<B / 64, 256, SMEM_C>>>(x, W1, b1, W2, b2, W3, b3, W4, out);
}

// round 15
// speedup vs baseline: 2.2765x; 1.4482x over previous
#include <cuda_runtime.h>

#define NSTEPS   50
#define T_DENSE  8
#define T_CACHED (NSTEPS - T_DENSE)
#define LRATE    0.1f
#define BMAX     8192

__device__ float g_c0[BMAX];
typedef unsigned long long u64;
typedef unsigned int u32;

__device__ __forceinline__ u64 pk2(float lo, float hi) {
    u64 r; asm("mov.b64 %0, {%1,%2};" : "=l"(r) : "f"(lo), "f"(hi)); return r;
}
__device__ __forceinline__ void upk2(u64 v, float& lo, float& hi) {
    asm("mov.b64 {%0,%1}, %2;" : "=f"(lo), "=f"(hi) : "l"(v));
}
__device__ __forceinline__ void fma2(u64& d, u64 a, u64 b) {
    asm("fma.rn.f32x2 %0, %1, %2, %0;" : "+l"(d) : "l"(a), "l"(b));
}
__device__ __forceinline__ u64 add2(u64 a, u64 b) {
    u64 r; asm("add.rn.f32x2 %0, %1, %2;" : "=l"(r) : "l"(a), "l"(b)); return r;
}

// ---------------- Kernel 1: 1-D nearest neighbor ----------------
#define NN_TILE 2048
__global__ __launch_bounds__(256) void nn_kernel(const float* __restrict__ c, int B) {
    __shared__ float ct[NN_TILE];
    int lane = threadIdx.x & 31, w = threadIdx.x >> 5, q = blockIdx.x * 8 + w;
    float cq = (q < B) ? c[q] : 0.f;
    float bestD = 3.0e38f; int bestJ = 0;
    for (int t0 = 0; t0 < B; t0 += NN_TILE) {
        int nt = min(NN_TILE, B - t0);
        __syncthreads();
        for (int i = threadIdx.x; i < nt; i += 256) ct[i] = c[t0 + i];
        __syncthreads();
        for (int jj = lane; jj < nt; jj += 32) {
            int j = t0 + jj;
            float d = fabsf(cq - ct[jj]);
            if (j == q) d += 1e9f;
            if (d < bestD) { bestD = d; bestJ = j; }
        }
    }
#pragma unroll
    for (int off = 16; off; off >>= 1) {
        float dO = __shfl_down_sync(0xffffffffu, bestD, off);
        int   jO = __shfl_down_sync(0xffffffffu, bestJ, off);
        if (dO < bestD || (dO == bestD && jO < bestJ)) { bestD = dO; bestJ = jO; }
    }
    if (lane == 0 && q < B) g_c0[q] = c[bestJ];
}

// ---------------- Phase 1: dense (R4 winner) ----------------
__device__ __forceinline__ void mv_d(const float* __restrict__ W,
                                     const u64* __restrict__ A,
                                     int n0, int sG2, u64 acc[16]) {
#pragma unroll 8
    for (int k = 0; k < 64; k++) {
        ulonglong2 wA  = *(const ulonglong2*)(W + k * 64 + n0);
        ulonglong2 wB  = *(const ulonglong2*)(W + k * 64 + n0 + 4);
        ulonglong2 h01 = *(const ulonglong2*)(A + k * 64 + sG2);
        ulonglong2 h23 = *(const ulonglong2*)(A + k * 64 + 32 + sG2);
        fma2(acc[0],  wA.x, h01.x); fma2(acc[1],  wA.x, h01.y);
        fma2(acc[2],  wA.x, h23.x); fma2(acc[3],  wA.x, h23.y);
        fma2(acc[4],  wA.y, h01.x); fma2(acc[5],  wA.y, h01.y);
        fma2(acc[6],  wA.y, h23.x); fma2(acc[7],  wA.y, h23.y);
        fma2(acc[8],  wB.x, h01.x); fma2(acc[9],  wB.x, h01.y);
        fma2(acc[10], wB.x, h23.x); fma2(acc[11], wB.x, h23.y);
        fma2(acc[12], wB.y, h01.x); fma2(acc[13], wB.y, h01.y);
        fma2(acc[14], wB.y, h23.x); fma2(acc[15], wB.y, h23.y);
    }
}
__device__ __forceinline__ void unpack_d(const u64 acc[16], float v[8][4]) {
#pragma unroll
    for (int p = 0; p < 4; p++)
#pragma unroll
        for (int si = 0; si < 4; si++)
            upk2(acc[p * 4 + si], v[2 * p][si], v[2 * p + 1][si]);
}
__device__ __forceinline__ void store_dup_d(u64* __restrict__ Y, int n0, int sG2,
                                            const float v[8][4]) {
#pragma unroll
    for (int r = 0; r < 8; r++) {
        ulonglong2 t0, t1;
        t0.x = pk2(v[r][0], v[r][0]); t0.y = pk2(v[r][1], v[r][1]);
        t1.x = pk2(v[r][2], v[r][2]); t1.y = pk2(v[r][3], v[r][3]);
        *(ulonglong2*)(Y + (n0 + r) * 64 + sG2)      = t0;
        *(ulonglong2*)(Y + (n0 + r) * 64 + 32 + sG2) = t1;
    }
}

__global__ __launch_bounds__(128, 1) void solver_dense(
    const float* __restrict__ x,
    const float* __restrict__ W1, const float* __restrict__ b1,
    const float* __restrict__ W2, const float* __restrict__ b2,
    const float* __restrict__ W3, const float* __restrict__ b3,
    const float* __restrict__ W4, float* __restrict__ out, int nsteps)
{
    extern __shared__ __align__(16) char smraw[];
    float* W2T = (float*)smraw;
    float* W3T = W2T + 4096;
    float* W2N = W3T + 4096;
    float* W3N = W2N + 4096;
    u64*  ActA = (u64*)(W3N + 4096);
    u64*  ActB = ActA + 4096;
    u64*  b2d  = ActB + 4096;
    u64*  b3d  = b2d + 32;
    float* red = (float*)(b3d + 32);

    int tid = threadIdx.x, lane = tid & 31, warp = tid >> 5;
    int sG = tid & 15, nG = tid >> 4, n0 = nG * 8, sG2 = sG * 2;

    for (int i = tid; i < 1024; i += 128) {
        ((float4*)W2N)[i] = ((const float4*)W2)[i];
        ((float4*)W3N)[i] = ((const float4*)W3)[i];
    }
    __syncthreads();
    for (int i = tid; i < 4096; i += 128) {
        int n = i >> 6, k = i & 63;
        W2T[k * 64 + n] = W2N[i];
        W3T[k * 64 + n] = W3N[i];
    }
    if (tid < 32) {
        b2d[tid] = pk2(b2[2 * tid], b2[2 * tid + 1]);
        b3d[tid] = pk2(b3[2 * tid], b3[2 * tid + 1]);
    }

    int gs = blockIdx.x * 64 + sG * 4;
    float xs[4], cs[4];
#pragma unroll
    for (int si = 0; si < 4; si++) { xs[si] = x[gs + si]; cs[si] = g_c0[gs + si]; }
    float a[8][4], w1y[8], w4r[8];
#pragma unroll
    for (int r = 0; r < 8; r++) {
        int n = n0 + r;
        float w1x = W1[n * 3], w1c = W1[n * 3 + 2], bb = b1[n];
        w1y[r] = W1[n * 3 + 1]; w4r[r] = W4[n];
#pragma unroll
        for (int si = 0; si < 4; si++)
            a[r][si] = fmaf(w1x, xs[si], fmaf(w1c, cs[si], bb));
    }
    __syncthreads();

    float y[4] = {0.f, 0.f, 0.f, 0.f};
    for (int step = 0; step < nsteps; step++) {
        unsigned m1 = 0;
        float v[8][4];
#pragma unroll
        for (int r = 0; r < 8; r++)
#pragma unroll
            for (int si = 0; si < 4; si++) {
                float z = fmaf(w1y[r], y[si], a[r][si]);
                if (z > 0.f) m1 |= 1u << (r * 4 + si);
                v[r][si] = fmaxf(z, 0.f);
            }
        store_dup_d(ActA, n0, sG2, v);
        __syncthreads();

        u64 acc[16];
        {
            ulonglong2 ba = *(const ulonglong2*)(b2d + nG * 4);
            ulonglong2 bb = *(const ulonglong2*)(b2d + nG * 4 + 2);
#pragma unroll
            for (int si = 0; si < 4; si++) {
                acc[si] = ba.x; acc[4 + si] = ba.y;
                acc[8 + si] = bb.x; acc[12 + si] = bb.y;
            }
        }
        mv_d(W2T, ActA, n0, sG2, acc);
        unsigned m2 = 0;
        unpack_d(acc, v);
#pragma unroll
        for (int r = 0; r < 8; r++)
#pragma unroll
            for (int si = 0; si < 4; si++) {
                if (v[r][si] > 0.f) m2 |= 1u << (r * 4 + si);
                v[r][si] = fmaxf(v[r][si], 0.f);
            }
        store_dup_d(ActB, n0, sG2, v);
        __syncthreads();

        {
            ulonglong2 ba = *(const ulonglong2*)(b3d + nG * 4);
            ulonglong2 bb = *(const ulonglong2*)(b3d + nG * 4 + 2);
#pragma unroll
            for (int si = 0; si < 4; si++) {
                acc[si] = ba.x; acc[4 + si] = ba.y;
                acc[8 + si] = bb.x; acc[12 + si] = bb.y;
            }
        }
        mv_d(W3T, ActB, n0, sG2, acc);
        unpack_d(acc, v);
#pragma unroll
        for (int r = 0; r < 8; r++)
#pragma unroll
            for (int si = 0; si < 4; si++)
                v[r][si] = (v[r][si] > 0.f) ? w4r[r] : 0.f;
        store_dup_d(ActA, n0, sG2, v);
        __syncthreads();

#pragma unroll
        for (int q = 0; q < 16; q++) acc[q] = 0;
        mv_d(W3N, ActA, n0, sG2, acc);
        unpack_d(acc, v);
#pragma unroll
        for (int r = 0; r < 8; r++)
#pragma unroll
            for (int si = 0; si < 4; si++)
                v[r][si] = (m2 & (1u << (r * 4 + si))) ? v[r][si] : 0.f;
        store_dup_d(ActB, n0, sG2, v);
        __syncthreads();

#pragma unroll
        for (int q = 0; q < 16; q++) acc[q] = 0;
        mv_d(W2N, ActB, n0, sG2, acc);
        unpack_d(acc, v);
        float pg[4] = {0.f, 0.f, 0.f, 0.f};
#pragma unroll
        for (int r = 0; r < 8; r++)
#pragma unroll
            for (int si = 0; si < 4; si++) {
                float g = (m1 & (1u << (r * 4 + si))) ? v[r][si] : 0.f;
                pg[si] = fmaf(w1y[r], g, pg[si]);
            }
#pragma unroll
        for (int si = 0; si < 4; si++)
            pg[si] += __shfl_xor_sync(0xffffffffu, pg[si], 16);
        if (!(lane & 16))
            *(float4*)(red + warp * 64 + sG * 4) = make_float4(pg[0], pg[1], pg[2], pg[3]);
        __syncthreads();
        {
            float4 r0 = *(const float4*)(red + 0 * 64 + sG * 4);
            float4 r1 = *(const float4*)(red + 1 * 64 + sG * 4);
            float4 r2 = *(const float4*)(red + 2 * 64 + sG * 4);
            float4 r3 = *(const float4*)(red + 3 * 64 + sG * 4);
            y[0] -= LRATE * ((r0.x + r1.x) + (r2.x + r3.x));
            y[1] -= LRATE * ((r0.y + r1.y) + (r2.y + r3.y));
            y[2] -= LRATE * ((r0.z + r1.z) + (r2.z + r3.z));
            y[3] -= LRATE * ((r0.w + r1.w) + (r2.w + r3.w));
        }
    }
    if (nG == 0)
        *(float4*)(out + gs) = make_float4(y[0], y[1], y[2], y[3]);
}

// ---------------- Phase 2: mask-region cached stepping ----------------
// Cold rebuild: per-lane masks only (no ballots); split FMA chains; writes
// RP2/RP3 + per-lane packed mask bits; returns warp-uniform gy.
__device__ __noinline__ float cold_build(
    const float* __restrict__ W2T, const float* __restrict__ W3T,
    const float* __restrict__ W2N, const float* __restrict__ W3N,
    const u64* __restrict__ b2p, const u64* __restrict__ b3p,
    float2* __restrict__ scf, u32* __restrict__ mkl,
    ulonglong2* __restrict__ rp2, ulonglong2* __restrict__ rp3,
    u64 apair, u64 w1yp, float w4lo, float w4hi, float y, int np)
{
    float* scu = (float*)scf;
    u64 ydup = pk2(y, y);
    u64 z1 = apair; fma2(z1, w1yp, ydup);
    float z1lo, z1hi; upk2(z1, z1lo, z1hi);
    bool m1lo = z1lo > 0.f, m1hi = z1hi > 0.f;
    float alo, ahi; upk2(apair, alo, ahi);
    float wylo, wyhi; upk2(w1yp, wylo, wyhi);
    scf[2 * np]     = make_float2(m1lo ? alo : 0.f, m1lo ? wylo : 0.f);
    scf[2 * np + 1] = make_float2(m1hi ? ahi : 0.f, m1hi ? wyhi : 0.f);
    __syncwarp();

    u64 Ra = b2p[np], Rb = 0, Pa = 0, Pb = 0;
#pragma unroll 4
    for (int k = 0; k < 32; k++) {
        float2 t0 = scf[k], t1 = scf[k + 32];
        u64 w0 = *(const u64*)(W2T + k * 64 + 2 * np);
        u64 w1 = *(const u64*)(W2T + (k + 32) * 64 + 2 * np);
        fma2(Ra, w0, pk2(t0.x, t0.x)); fma2(Pa, w0, pk2(t0.y, t0.y));
        fma2(Rb, w1, pk2(t1.x, t1.x)); fma2(Pb, w1, pk2(t1.y, t1.y));
    }
    u64 R2 = add2(Ra, Rb), P2 = add2(Pa, Pb);
    { ulonglong2 t; t.x = R2; t.y = P2; rp2[np] = t; }
    u64 z2 = R2; fma2(z2, P2, ydup);
    float z2lo, z2hi; upk2(z2, z2lo, z2hi);
    bool m2lo = z2lo > 0.f, m2hi = z2hi > 0.f;
    float rlo, rhi, plo, phi; upk2(R2, rlo, rhi); upk2(P2, plo, phi);
    __syncwarp();
    scf[2 * np]     = make_float2(m2lo ? rlo : 0.f, m2lo ? plo : 0.f);
    scf[2 * np + 1] = make_float2(m2hi ? rhi : 0.f, m2hi ? phi : 0.f);
    __syncwarp();

    Ra = b3p[np]; Rb = 0; Pa = 0; Pb = 0;
#pragma unroll 4
    for (int k = 0; k < 32; k++) {
        float2 t0 = scf[k], t1 = scf[k + 32];
        u64 w0 = *(const u64*)(W3T + k * 64 + 2 * np);
        u64 w1 = *(const u64*)(W3T + (k + 32) * 64 + 2 * np);
        fma2(Ra, w0, pk2(t0.x, t0.x)); fma2(Pa, w0, pk2(t0.y, t0.y));
        fma2(Rb, w1, pk2(t1.x, t1.x)); fma2(Pb, w1, pk2(t1.y, t1.y));
    }
    u64 R3 = add2(Ra, Rb), P3 = add2(Pa, Pb);
    { ulonglong2 t; t.x = R3; t.y = P3; rp3[np] = t; }
    u64 z3 = R3; fma2(z3, P3, ydup);
    float z3lo, z3hi; upk2(z3, z3lo, z3hi);
    bool m3lo = z3lo > 0.f, m3hi = z3hi > 0.f;

    mkl[np] = (m1lo ? 1u : 0u) | (m1hi ? 2u : 0u) | (m2lo ? 4u : 0u)
            | (m2hi ? 8u : 0u) | (m3lo ? 16u : 0u) | (m3hi ? 32u : 0u);

    // backward (mask-only)
    __syncwarp();
    scu[2 * np]     = m3lo ? w4lo : 0.f;
    scu[2 * np + 1] = m3hi ? w4hi : 0.f;
    __syncwarp();
    u64 ta = 0, tb = 0;
#pragma unroll 4
    for (int j = 0; j < 32; j++) {
        float u0 = scu[j], u1 = scu[j + 32];
        fma2(ta, *(const u64*)(W3N + j * 64 + 2 * np), pk2(u0, u0));
        fma2(tb, *(const u64*)(W3N + (j + 32) * 64 + 2 * np), pk2(u1, u1));
    }
    u64 tt = add2(ta, tb);
    float tlo, thi; upk2(tt, tlo, thi);
    __syncwarp();
    scu[2 * np]     = m2lo ? tlo : 0.f;
    scu[2 * np + 1] = m2hi ? thi : 0.f;
    __syncwarp();
    ta = 0; tb = 0;
#pragma unroll 4
    for (int j = 0; j < 32; j++) {
        float v0 = scu[j], v1 = scu[j + 32];
        fma2(ta, *(const u64*)(W2N + j * 64 + 2 * np), pk2(v0, v0));
        fma2(tb, *(const u64*)(W2N + (j + 32) * 64 + 2 * np), pk2(v1, v1));
    }
    tt = add2(ta, tb);
    float wlo, whi; upk2(tt, wlo, whi);
    float pg = (m1lo ? wylo * wlo : 0.f) + (m1hi ? wyhi * whi : 0.f);
#pragma unroll
    for (int o = 1; o < 32; o <<= 1) pg += __shfl_xor_sync(0xffffffffu, pg, o);
    return pg;
}

__global__ __launch_bounds__(256, 1) void solver_cached(
    const float* __restrict__ x,
    const float* __restrict__ W1, const float* __restrict__ b1,
    const float* __restrict__ W2, const float* __restrict__ b2,
    const float* __restrict__ W3, const float* __restrict__ b3,
    const float* __restrict__ W4, float* __restrict__ out)
{
    extern __shared__ __align__(16) char sm[];
    float* W2T = (float*)sm;
    float* W3T = W2T + 4096;
    float* W2N = W3T + 4096;
    float* W3N = W2N + 4096;
    u64*   b2p = (u64*)(W3N + 4096);
    u64*   b3p = b2p + 32;
    ulonglong2* RP2 = (ulonglong2*)(b3p + 32);   // [128 entries][32 lanes]
    ulonglong2* RP3 = RP2 + 128 * 32;
    float2* SCF = (float2*)(RP3 + 128 * 32);     // [8 warps][64]
    u32*   MKL  = (u32*)(SCF + 8 * 64);          // [128 entries][32 lanes]

    int tid = threadIdx.x, np = tid & 31, w = tid >> 5;

    for (int i = tid; i < 1024; i += 256) {
        ((float4*)W2N)[i] = ((const float4*)W2)[i];
        ((float4*)W3N)[i] = ((const float4*)W3)[i];
    }
    __syncthreads();
    for (int i = tid; i < 4096; i += 256) {
        int n = i >> 6, k = i & 63;
        W2T[k * 64 + n] = W2N[i];
        W3T[k * 64 + n] = W3N[i];
    }
    if (tid < 32) {
        b2p[tid] = pk2(b2[2 * tid], b2[2 * tid + 1]);
        b3p[tid] = pk2(b3[2 * tid], b3[2 * tid + 1]);
    }
    __syncthreads();

    int gs = blockIdx.x * 64 + w * 8;
    float wy_lo = W1[(2 * np) * 3 + 1], wy_hi = W1[(2 * np + 1) * 3 + 1];
    u64 w1yp = pk2(wy_lo, wy_hi);
    float w4lo = W4[2 * np], w4hi = W4[2 * np + 1];
    float w1x0 = W1[(2 * np) * 3], w1c0 = W1[(2 * np) * 3 + 2], bb0 = b1[2 * np];
    float w1x1 = W1[(2 * np + 1) * 3], w1c1 = W1[(2 * np + 1) * 3 + 2], bb1 = b1[2 * np + 1];

    u64 ap[8]; float ys[8];
#pragma unroll
    for (int s = 0; s < 8; s++) {
        float xv = x[gs + s], cv = g_c0[gs + s];
        ap[s] = pk2(fmaf(w1x0, xv, fmaf(w1c0, cv, bb0)),
                    fmaf(w1x1, xv, fmaf(w1c1, cv, bb1)));
        ys[s] = out[gs + s];
    }
    float2* scf = SCF + w * 64;
    float g0[8], g1[8];
    u32 validBits = 0, mruBits = 0;      // warp-uniform

    for (int t = 0; t < T_CACHED; t++) {
#pragma unroll
        for (int s = 0; s < 8; s++) {
            float y = ys[s];
            u64 ydup = pk2(y, y);
            u64 z1 = ap[s]; fma2(z1, w1yp, ydup);
            float z1lo, z1hi; upk2(z1, z1lo, z1hi);
            unsigned cur1 = (z1lo > 0.f ? 1u : 0u) | (z1hi > 0.f ? 2u : 0u);

            int e0 = (mruBits >> s) & 1;
            int hitE = -1;
#pragma unroll
            for (int tr = 0; tr < 2; tr++) {
                if (hitE >= 0) continue;
                int e = e0 ^ tr;
                if (!((validBits >> (e * 8 + s)) & 1)) continue;
                int base = (w * 2 + e) * 8 + s;
                u32 mb = MKL[base * 32 + np];
                ulonglong2 r2 = RP2[base * 32 + np];
                ulonglong2 r3 = RP3[base * 32 + np];
                u64 z2 = r2.x; fma2(z2, r2.y, ydup);
                u64 z3 = r3.x; fma2(z3, r3.y, ydup);
                float z2lo, z2hi, z3lo, z3hi;
                upk2(z2, z2lo, z2hi); upk2(z3, z3lo, z3hi);
                unsigned cur = cur1 | (z2lo > 0.f ? 4u : 0u) | (z2hi > 0.f ? 8u : 0u)
                             | (z3lo > 0.f ? 16u : 0u) | (z3hi > 0.f ? 32u : 0u);
                if (__ballot_sync(0xffffffffu, cur == mb) == 0xffffffffu) hitE = e;
            }

            if (hitE >= 0) {
                y -= LRATE * (hitE ? g1[s] : g0[s]);
                mruBits = (mruBits & ~(1u << s)) | ((u32)hitE << s);
            } else {
                int e = e0 ^ 1;
                int base = (w * 2 + e) * 8 + s;
                float gy = cold_build(W2T, W3T, W2N, W3N, b2p, b3p, scf,
                                      MKL + base * 32, RP2 + base * 32,
                                      RP3 + base * 32,
                                      ap[s], w1yp, w4lo, w4hi, y, np);
                if (e) g1[s] = gy; else g0[s] = gy;
                validBits |= 1u << (e * 8 + s);
                mruBits = (mruBits & ~(1u << s)) | ((u32)e << s);
                y -= LRATE * gy;
            }
            ys[s] = y;
        }
    }

    if (np == 0) {
#pragma unroll
        for (int s = 0; s < 8; s++) out[gs + s] = ys[s];
    }
}

// ---------------- Launch ----------------
extern "C" void kernel_launch(void* const* d_in, const int* in_sizes, int n_in,
                              void* d_out, int out_size) {
    const float* x  = (const float*)d_in[0];
    const float* c  = (const float*)d_in[1];
    const float* W1 = (const float*)d_in[2];
    const float* b1 = (const float*)d_in[3];
    const float* W2 = (const float*)d_in[4];
    const float* b2 = (const float*)d_in[5];
    const float* W3 = (const float*)d_in[6];
    const float* b3 = (const float*)d_in[7];
    const float* W4 = (const float*)d_in[8];
    float* out = (float*)d_out;
    int B = in_sizes[0];

    const int SMEM_D = 4 * 4096 * 4 + 2 * 4096 * 8 + 64 * 8 + 256 * 4;   // 132608
    const int SMEM_C = 4 * 4096 * 4 + 64 * 8 + 2 * 128 * 32 * 16
                     + 8 * 64 * 8 + 128 * 32 * 4;                        // 217600
    cudaFuncSetAttribute(solver_dense,
                         cudaFuncAttributeMaxDynamicSharedMemorySize, SMEM_D);
    cudaFuncSetAttribute(solver_cached,
                         cudaFuncAttributeMaxDynamicSharedMemorySize, SMEM_C);

    nn_kernel<<<(B + 7) / 8, 256>>>(c, B);
    solver_dense<<<B / 64, 128, SMEM_D>>>(x, W1, b1, W2, b2, W3, b3, W4, out, T_DENSE);
    solver_cached<<<B / 64, 256, SMEM_C>>>(x, W1, b1, W2, b2, W3, b3, W4, out);
}